// round 12
// baseline (speedup 1.0000x reference)
#include <cuda_runtime.h>
#include <cuda_bf16.h>
#include <math.h>
#include <stdint.h>

// Problem constants
#define Bsz   8
#define Esz   256
#define Nsz   32
#define Dsz   512
#define RDsz  768
#define Rsz   2000
#define Lsz   2
#define Ksel  8
#define Msz   32
#define Hsz   8
#define DHsz  64
#define HLLMsz 4096
#define BE    (Bsz*Esz)   // 2048
#define DD    (Dsz*Dsz)

// fp32 scratch
__device__ float g_ptable[Rsz*Dsz];
__device__ float g_norms[Rsz];
__device__ float g_states[BE*Dsz];
__device__ float g_tmp[BE*Dsz];
__device__ float g_tmp2[BE*Dsz];
__device__ float g_q[Msz*Dsz];
__device__ float g_kv[BE*2*Dsz];
__device__ float g_bc[Lsz*Dsz];
__device__ float g_kvb[2*Dsz];
__device__ float g_zero[Dsz];          // stays zero (static zero-init)

// bf16 hi/lo split scratch
__device__ __nv_bfloat16 g_relh[Rsz*RDsz],      g_rell[Rsz*RDsz];
__device__ __nv_bfloat16 g_rpwh[Dsz*RDsz],      g_rpwl[Dsz*RDsz];
__device__ __nv_bfloat16 g_vwTh[Lsz*DD],        g_vwTl[Lsz*DD];
__device__ __nv_bfloat16 g_owh[Lsz*DD],         g_owl[Lsz*DD];
__device__ __nv_bfloat16 g_wch[Lsz*DD],         g_wcl[Lsz*DD];
__device__ __nv_bfloat16 g_w1h[Lsz*4*DD],       g_w1l[Lsz*4*DD];
__device__ __nv_bfloat16 g_w2h[Lsz*4*DD],       g_w2l[Lsz*4*DD];
__device__ __nv_bfloat16 g_tqwh[DD],            g_tqwl[DD];
__device__ __nv_bfloat16 g_kvwh[2*DD],          g_kvwl[2*DD];
__device__ __nv_bfloat16 g_towh[DD],            g_towl[DD];
__device__ __nv_bfloat16 g_pwh[HLLMsz*Dsz],     g_pwl[HLLMsz*Dsz];
__device__ __nv_bfloat16 g_memqh[Msz*Dsz],      g_memql[Msz*Dsz];
__device__ __nv_bfloat16 g_aggh[BE*Dsz],        g_aggl[BE*Dsz];
__device__ __nv_bfloat16 g_sth[BE*Dsz],         g_stl[BE*Dsz];
__device__ __nv_bfloat16 g_hidh[BE*4*Dsz],      g_hidl[BE*4*Dsz];
__device__ __nv_bfloat16 g_memh[Bsz*Msz*Dsz],   g_meml[Bsz*Msz*Dsz];
__device__ __nv_bfloat16 g_m2h[Bsz*Msz*Dsz],    g_m2l[Bsz*Msz*Dsz];

// ---------------------------------------------------------------------------
__device__ __forceinline__ uint32_t smem_u32(const void* p) {
    uint32_t a;
    asm("{ .reg .u64 t; cvta.to.shared.u64 t, %1; cvt.u32.u64 %0, t; }"
        : "=r"(a) : "l"(p));
    return a;
}

__device__ __forceinline__ void mma_bf16(float* c, const uint32_t* a, const uint32_t* b)
{
    asm volatile(
        "mma.sync.aligned.m16n8k16.row.col.f32.bf16.bf16.f32 "
        "{%0,%1,%2,%3}, {%4,%5,%6,%7}, {%8,%9}, {%0,%1,%2,%3};"
        : "+f"(c[0]), "+f"(c[1]), "+f"(c[2]), "+f"(c[3])
        : "r"(a[0]), "r"(a[1]), "r"(a[2]), "r"(a[3]), "r"(b[0]), "r"(b[1]));
}

__device__ __forceinline__ void ldm4(uint32_t* d, uint32_t addr)
{
    asm volatile("ldmatrix.sync.aligned.m8n8.x4.shared.b16 {%0,%1,%2,%3}, [%4];"
        : "=r"(d[0]), "=r"(d[1]), "=r"(d[2]), "=r"(d[3]) : "r"(addr));
}

__device__ __forceinline__ void split2(float x, float y, uint32_t& hi, uint32_t& lo)
{
    __nv_bfloat162 h = __floats2bfloat162_rn(x, y);
    float2 hf = __bfloat1622float2(h);
    __nv_bfloat162 l = __floats2bfloat162_rn(x - hf.x, y - hf.y);
    hi = *reinterpret_cast<uint32_t*>(&h);
    lo = *reinterpret_cast<uint32_t*>(&l);
}

__device__ __forceinline__ void split_scalar(float v, __nv_bfloat16* hp, __nv_bfloat16* lp)
{
    __nv_bfloat16 h = __float2bfloat16(v);
    *hp = h;
    *lp = __float2bfloat16(v - __bfloat162float(h));
}

#define CP_ASYNC16(dst, src) \
    asm volatile("cp.async.cg.shared.global [%0], [%1], 16;" :: "r"(dst), "l"(src))
#define CP_COMMIT() asm volatile("cp.async.commit_group;" ::: "memory")

// ---------------------------------------------------------------------------
// Batched fp32 -> (hi,lo) bf16 split.
// ---------------------------------------------------------------------------
struct SJobs {
    const float4* src[12];
    uint2* hi[12];
    uint2* lo[12];
    unsigned end4[12];
    int cnt;
    unsigned total4;
};

__global__ __launch_bounds__(256)
void split_multi(SJobs jb)
{
    unsigned idx = blockIdx.x * 256u + threadIdx.x;
    if (idx >= jb.total4) return;
    int t = 0;
#pragma unroll 1
    for (int i = 0; i < jb.cnt; i++)
        if (idx < jb.end4[i]) { t = i; break; }
    unsigned start = (t == 0) ? 0u : jb.end4[t - 1];
    unsigned li = idx - start;
    float4 v = jb.src[t][li];
    uint32_t h0, l0, h1, l1;
    split2(v.x, v.y, h0, l0);
    split2(v.z, v.w, h1, l1);
    jb.hi[t][li] = make_uint2(h0, h1);
    jb.lo[t][li] = make_uint2(l0, l1);
}

// transpose-split: vw[l][t][j] -> vwT[l][j][t] as bf16 hi/lo
__global__ __launch_bounds__(256)
void transpose_split_vw(const float* __restrict__ vw)
{
    __shared__ float tile[32][33];
    int l = blockIdx.z;
    int tx = threadIdx.x, ty = threadIdx.y;
#pragma unroll
    for (int i = 0; i < 32; i += 8) {
        int trow = blockIdx.y * 32 + ty + i;
        int jcol = blockIdx.x * 32 + tx;
        tile[ty + i][tx] = vw[(size_t)l * DD + (size_t)trow * Dsz + jcol];
    }
    __syncthreads();
#pragma unroll
    for (int i = 0; i < 32; i += 8) {
        int jrow = blockIdx.x * 32 + ty + i;
        int tcol = blockIdx.y * 32 + tx;
        float v = tile[tx][ty + i];
        size_t o = (size_t)l * DD + (size_t)jrow * Dsz + tcol;
        split_scalar(v, &g_vwTh[o], &g_vwTl[o]);
    }
}

// bc[l] = ow[l] @ vb[l] + ob[l]; last block concatenates kv bias
__global__ __launch_bounds__(256)
void bc_concat(const float* __restrict__ ow, const float* __restrict__ vb,
               const float* __restrict__ ob,
               const float* __restrict__ tkb, const float* __restrict__ tvb)
{
    if (blockIdx.x == Lsz * 64) {
        for (int i = threadIdx.x; i < Dsz; i += 256) {
            g_kvb[i] = tkb[i];
            g_kvb[Dsz + i] = tvb[i];
        }
        return;
    }
    int l = blockIdx.x / 64;
    int d = (blockIdx.x % 64) * 8 + (threadIdx.x >> 5);
    int lane = threadIdx.x & 31;
    const float* owr = ow + (size_t)l * DD + (size_t)d * Dsz;
    const float* vbr = vb + l * Dsz;
    float s = 0.f;
#pragma unroll 4
    for (int t = lane; t < Dsz; t += 32)
        s = fmaf(owr[t], vbr[t], s);
    for (int o = 16; o; o >>= 1) s += __shfl_xor_sync(0xffffffffu, s, o);
    if (lane == 0)
        g_bc[l * Dsz + d] = s + ob[l * Dsz + d];
}

// ---------------------------------------------------------------------------
// bf16x3 emulated-fp32 GEMM on mma.sync.m16n8k16 + ldmatrix.x4 + cp.async.
// Pre-split bf16 (hi,lo) operands. C = A @ W^T + bias (opt exact GELU).
// 256 threads = 8 warps as 4(m) x 2(n). BM=MT*64, BN=NT*16, BK=32, 3 stages.
// ---------------------------------------------------------------------------
template<int MT, int NT, bool GELU, bool WSPLIT, bool WF32>
__global__ __launch_bounds__(256)
void mma_gemm(const __nv_bfloat16* __restrict__ Ah, const __nv_bfloat16* __restrict__ Al,
              const __nv_bfloat16* __restrict__ Wh, const __nv_bfloat16* __restrict__ Wl,
              const float* __restrict__ bias, float* __restrict__ C,
              __nv_bfloat16* __restrict__ Chi, __nv_bfloat16* __restrict__ Clo,
              int Mm, int Nn, int Kk)
{
    constexpr int BM    = MT * 64;
    constexpr int BN    = NT * 16;
    constexpr int ROWS  = BM + BN;
    constexpr int CHc   = ROWS * 8 / 256;
    constexpr int BUF   = ROWS * 64;
    constexpr int PAIRS = NT / 2;

    extern __shared__ char smraw[];
    const uint32_t sbase = smem_u32(smraw);

    const int tid  = threadIdx.x;
    const int lane = tid & 31;
    const int wid  = tid >> 5;
    const int m0 = blockIdx.y * BM;
    const int n0 = blockIdx.x * BN;
    const int mw = (wid >> 1) * (MT * 16);
    const int nw = (wid & 1) * (NT * 8);
    const int r  = lane >> 2;
    const int cq = lane & 3;

    float acc[MT][NT][4];
#pragma unroll
    for (int mt = 0; mt < MT; mt++)
#pragma unroll
        for (int j = 0; j < NT; j++)
#pragma unroll
            for (int t = 0; t < 4; t++) acc[mt][j][t] = 0.f;

    const __nv_bfloat16* gp[CHc];
    bool val[CHc];
    uint32_t soff[CHc];
#pragma unroll
    for (int i = 0; i < CHc; i++) {
        int idx = i * 256 + tid;
        int b   = idx >= ROWS * 4;
        int rem = idx - b * ROWS * 4;
        int rr  = rem >> 2;
        int q   = rem & 3;
        soff[i] = (uint32_t)(b * BUF + rr * 64 + ((q ^ ((rr >> 1) & 3)) * 16));
        const __nv_bfloat16* src;
        int grow;
        if (rr < BM) { src = b ? Al : Ah; grow = m0 + rr; val[i] = grow < Mm; }
        else         { src = b ? Wl : Wh; grow = n0 + rr - BM; val[i] = true; }
        gp[i] = src + (size_t)grow * Kk + q * 8;
    }

    const int rrA0 = mw + ((lane >> 3) & 1) * 8 + (lane & 7);
    uint32_t arow[MT];
    int aswz[MT];
#pragma unroll
    for (int mt = 0; mt < MT; mt++) {
        int rr = rrA0 + mt * 16;
        arow[mt] = (uint32_t)(rr * 64);
        aswz[mt] = (rr >> 1) & 3;
    }
    const int akk = lane >> 4;
    uint32_t brow[PAIRS];
    int bswz[PAIRS];
    const int bkk = (lane >> 3) & 1;
#pragma unroll
    for (int p = 0; p < PAIRS; p++) {
        int rrB = BM + nw + (p * 2 + (lane >> 4)) * 8 + (lane & 7);
        brow[p] = (uint32_t)(rrB * 64);
        bswz[p] = (rrB >> 1) & 3;
    }

    const int nkt = Kk >> 5;

#pragma unroll
    for (int i = 0; i < CHc; i++)
        if (val[i]) CP_ASYNC16(sbase + soff[i], gp[i]);
    CP_COMMIT();
    {
        const uint32_t dst = sbase + (uint32_t)2 * BUF;
#pragma unroll
        for (int i = 0; i < CHc; i++)
            if (val[i]) CP_ASYNC16(dst + soff[i], gp[i] + 32);
    }
    CP_COMMIT();

#pragma unroll 1
    for (int kt = 0; kt < nkt; kt++) {
        asm volatile("cp.async.wait_group 1;" ::: "memory");
        __syncthreads();
        if (kt + 2 < nkt) {
            const int sn = (kt + 2) % 3;
            const uint32_t dst = sbase + (uint32_t)(sn * 2) * BUF;
            const size_t koff = (size_t)(kt + 2) * 32;
#pragma unroll
            for (int i = 0; i < CHc; i++)
                if (val[i]) CP_ASYNC16(dst + soff[i], gp[i] + koff);
        }
        CP_COMMIT();

        const int s = kt % 3;
        const uint32_t Hb = sbase + (uint32_t)(s * 2) * BUF;
        const uint32_t Lb = Hb + BUF;
#pragma unroll
        for (int ks = 0; ks < 2; ks++) {
            uint32_t ah[MT][4], al[MT][4];
#pragma unroll
            for (int mt = 0; mt < MT; mt++) {
                const uint32_t ak = (uint32_t)(((ks * 2 + akk) ^ aswz[mt]) * 16);
                ldm4(ah[mt], Hb + arow[mt] + ak);
                ldm4(al[mt], Lb + arow[mt] + ak);
            }
#pragma unroll
            for (int p = 0; p < PAIRS; p++) {
                uint32_t bh[4], bl[4];
                const uint32_t bk = (uint32_t)(((ks * 2 + bkk) ^ bswz[p]) * 16);
                ldm4(bh, Hb + brow[p] + bk);
                ldm4(bl, Lb + brow[p] + bk);
#pragma unroll
                for (int t = 0; t < 2; t++) {
                    const int j = p * 2 + t;
#pragma unroll
                    for (int mt = 0; mt < MT; mt++) {
                        mma_bf16(acc[mt][j], ah[mt], bh + 2 * t);
                        mma_bf16(acc[mt][j], al[mt], bh + 2 * t);
                        mma_bf16(acc[mt][j], ah[mt], bl + 2 * t);
                    }
                }
            }
        }
    }

#pragma unroll
    for (int mt = 0; mt < MT; mt++) {
        const int row0 = m0 + mw + mt * 16 + r;
#pragma unroll
        for (int j = 0; j < NT; j++) {
            const int col = n0 + nw + j * 8 + cq * 2;
            const float b0v = __ldg(&bias[col]);
            const float b1v = __ldg(&bias[col + 1]);
            float v0 = acc[mt][j][0] + b0v;
            float v1 = acc[mt][j][1] + b1v;
            float v2 = acc[mt][j][2] + b0v;
            float v3 = acc[mt][j][3] + b1v;
            if (GELU) {
                v0 = 0.5f * v0 * (1.f + erff(v0 * 0.70710678118654752f));
                v1 = 0.5f * v1 * (1.f + erff(v1 * 0.70710678118654752f));
                v2 = 0.5f * v2 * (1.f + erff(v2 * 0.70710678118654752f));
                v3 = 0.5f * v3 * (1.f + erff(v3 * 0.70710678118654752f));
            }
            if (row0 < Mm) {
                const size_t o = (size_t)row0 * Nn + col;
                if (WF32) { C[o] = v0; C[o + 1] = v1; }
                if (WSPLIT) {
                    uint32_t h, l; split2(v0, v1, h, l);
                    *(uint32_t*)&Chi[o] = h; *(uint32_t*)&Clo[o] = l;
                }
            }
            if (row0 + 8 < Mm) {
                const size_t o = (size_t)(row0 + 8) * Nn + col;
                if (WF32) { C[o] = v2; C[o + 1] = v3; }
                if (WSPLIT) {
                    uint32_t h, l; split2(v2, v3, h, l);
                    *(uint32_t*)&Chi[o] = h; *(uint32_t*)&Clo[o] = l;
                }
            }
        }
    }
}

// ---------------------------------------------------------------------------
__device__ __forceinline__ float block_sum_256(float v, float* red)
{
    for (int o = 16; o; o >>= 1) v += __shfl_xor_sync(0xffffffffu, v, o);
    int w = threadIdx.x >> 5;
    if ((threadIdx.x & 31) == 0) red[w] = v;
    __syncthreads();
    float r = 0.f;
    if (threadIdx.x < 8) {
        r = red[threadIdx.x];
        for (int o = 4; o; o >>= 1) r += __shfl_xor_sync(0xffu, r, o);
        if (threadIdx.x == 0) red[0] = r;
    }
    __syncthreads();
    r = red[0];
    __syncthreads();
    return r;
}

__global__ __launch_bounds__(128)
void row_norm_kernel()
{
    int r = blockIdx.x;
    int tid = threadIdx.x;
    float4 v = ((const float4*)&g_ptable[(size_t)r * Dsz])[tid];
    float s = v.x*v.x + v.y*v.y + v.z*v.z + v.w*v.w;
    for (int o = 16; o; o >>= 1) s += __shfl_xor_sync(0xffffffffu, s, o);
    __shared__ float red[4];
    if ((tid & 31) == 0) red[tid >> 5] = s;
    __syncthreads();
    if (tid == 0)
        g_norms[r] = sqrtf(red[0] + red[1] + red[2] + red[3]);
}

__global__ __launch_bounds__(256)
void sim_topk_agg(const int* __restrict__ eids, const int* __restrict__ nids)
{
    int be = blockIdx.x;
    int tid = threadIdx.x;
    __shared__ float4 ev4[Dsz / 4];
    __shared__ float sims[Nsz];
    __shared__ int   selnid[Ksel];
    int eid = eids[be];
    if (tid < 128)
        ev4[tid] = ((const float4*)&g_ptable[(size_t)eid * Dsz])[tid];
    __syncthreads();
    float enorm = fmaxf(g_norms[eid], 1e-12f);
    int warp = tid >> 5, lane = tid & 31;
    // 4 neighbors per warp, interleaved loads for MLP=4
    int nid[4];
    const float4* nv[4];
#pragma unroll
    for (int t = 0; t < 4; t++) {
        nid[t] = nids[be * Nsz + warp * 4 + t];
        nv[t]  = (const float4*)&g_ptable[(size_t)nid[t] * Dsz];
    }
    float accv[4] = {0.f, 0.f, 0.f, 0.f};
#pragma unroll
    for (int j = 0; j < 4; j++) {
        float4 b = ev4[lane + 32 * j];
#pragma unroll
        for (int t = 0; t < 4; t++) {
            float4 a = nv[t][lane + 32 * j];
            accv[t] = fmaf(a.x, b.x, accv[t]);
            accv[t] = fmaf(a.y, b.y, accv[t]);
            accv[t] = fmaf(a.z, b.z, accv[t]);
            accv[t] = fmaf(a.w, b.w, accv[t]);
        }
    }
#pragma unroll
    for (int t = 0; t < 4; t++) {
        float s = accv[t];
        for (int o = 16; o; o >>= 1) s += __shfl_xor_sync(0xffffffffu, s, o);
        if (lane == 0)
            sims[warp * 4 + t] = s / (enorm * fmaxf(g_norms[nid[t]], 1e-12f));
    }
    __syncthreads();
    if (tid == 0) {
        unsigned used = 0;
        for (int j = 0; j < Ksel; j++) {
            float best = -3.402823466e38f; int bi = 0;
            for (int n = 0; n < Nsz; n++)
                if (!((used >> n) & 1u) && sims[n] > best) { best = sims[n]; bi = n; }
            used |= 1u << bi;
            selnid[j] = nids[be * Nsz + bi];
        }
    }
    __syncthreads();
    float2 s2 = make_float2(0.f, 0.f);
#pragma unroll
    for (int j = 0; j < Ksel; j++) {
        float2 vq = ((const float2*)&g_ptable[(size_t)selnid[j] * Dsz])[tid];
        s2.x += vq.x; s2.y += vq.y;
    }
    s2.x *= 0.125f; s2.y *= 0.125f;
    const size_t o = (size_t)be * Dsz + tid * 2;
    uint32_t h, l;
    split2(s2.x, s2.y, h, l);
    *(uint32_t*)&g_aggh[o] = h;
    *(uint32_t*)&g_aggl[o] = l;
}

__global__ __launch_bounds__(256)
void add_ln(const float* __restrict__ x, const int* __restrict__ xidx,
            const float* __restrict__ add,
            float* __restrict__ out, const float* __restrict__ g,
            const float* __restrict__ b, const float* __restrict__ mask)
{
    int row = blockIdx.x;
    int tid = threadIdx.x;
    __shared__ float red[8];
    size_t base = (size_t)row * Dsz;
    const float* xr = xidx ? &g_ptable[(size_t)xidx[row] * Dsz] : &x[base];
    float v0 = xr[tid]       + add[base + tid];
    float v1 = xr[tid + 256] + add[base + tid + 256];
    float total = block_sum_256(v0 + v1, red);
    float mu = total * (1.f / Dsz);
    float d0 = v0 - mu, d1 = v1 - mu;
    float var = block_sum_256(d0*d0 + d1*d1, red) * (1.f / Dsz);
    float inv = rsqrtf(var + 1e-5f);
    float mk = mask ? mask[row] : 1.f;
    float o0 = (d0 * inv * g[tid]       + b[tid])       * mk;
    float o1 = (d1 * inv * g[tid + 256] + b[tid + 256]) * mk;
    out[base + tid]       = o0;
    out[base + tid + 256] = o1;
    split_scalar(o0, &g_sth[base + tid],       &g_stl[base + tid]);
    split_scalar(o1, &g_sth[base + tid + 256], &g_stl[base + tid + 256]);
}

__global__ __launch_bounds__(256)
void mem_attn(const float* __restrict__ mask)
{
    int b = blockIdx.x >> 5;
    int m = blockIdx.x & 31;
    int tid = threadIdx.x;
    __shared__ float qs[Dsz];
    __shared__ float sc[Hsz][Esz];
    qs[tid]       = g_q[m*Dsz + tid];
    qs[tid + 256] = g_q[m*Dsz + tid + 256];
    __syncthreads();
    {
        int e = tid;
        const float* kr = &g_kv[((size_t)b*Esz + e) * (2*Dsz)];
        float mk = mask[b*Esz + e];
#pragma unroll
        for (int h = 0; h < Hsz; h++) {
            float s = 0.f;
#pragma unroll
            for (int d = 0; d < DHsz; d += 4) {
                float4 kq = *(const float4*)&kr[h*DHsz + d];
                float4 qq = *(const float4*)&qs[h*DHsz + d];
                s = fmaf(kq.x, qq.x, s); s = fmaf(kq.y, qq.y, s);
                s = fmaf(kq.z, qq.z, s); s = fmaf(kq.w, qq.w, s);
            }
            s *= 0.125f;
            sc[h][e] = (mk == 0.f) ? -3.402823466e38f : s;
        }
    }
    __syncthreads();
    {
        int w = tid >> 5, lane = tid & 31;
        float vals[8];
        float mx = -3.402823466e38f;
#pragma unroll
        for (int j = 0; j < 8; j++) { vals[j] = sc[w][lane + 32*j]; mx = fmaxf(mx, vals[j]); }
        for (int o = 16; o; o >>= 1) mx = fmaxf(mx, __shfl_xor_sync(0xffffffffu, mx, o));
        float sm = 0.f;
#pragma unroll
        for (int j = 0; j < 8; j++) { vals[j] = expf(vals[j] - mx); sm += vals[j]; }
        for (int o = 16; o; o >>= 1) sm += __shfl_xor_sync(0xffffffffu, sm, o);
        float inv = 1.f / sm;
#pragma unroll
        for (int j = 0; j < 8; j++) sc[w][lane + 32*j] = vals[j] * inv;
    }
    __syncthreads();
    float a0 = 0.f, a1 = 0.f;
    int od0 = tid, od1 = tid + 256;
    int h0 = od0 >> 6, h1 = od1 >> 6;
    for (int e = 0; e < Esz; e++) {
        const float* vr = &g_kv[((size_t)b*Esz + e) * (2*Dsz) + Dsz];
        a0 = fmaf(sc[h0][e], vr[od0], a0);
        a1 = fmaf(sc[h1][e], vr[od1], a1);
    }
    size_t ob = (size_t)blockIdx.x * Dsz;
    split_scalar(a0, &g_memh[ob + od0], &g_meml[ob + od0]);
    split_scalar(a1, &g_memh[ob + od1], &g_meml[ob + od1]);
}

__global__ __launch_bounds__(256)
void zero_noedge(const float* __restrict__ mask)
{
    int b = blockIdx.x;
    __shared__ float red[8];
    float total = block_sum_256(mask[b*Esz + threadIdx.x], red);
    if (total == 0.f) {
        uint32_t* h = (uint32_t*)&g_m2h[(size_t)b*Msz*Dsz];
        uint32_t* l = (uint32_t*)&g_m2l[(size_t)b*Msz*Dsz];
        for (int i = threadIdx.x; i < Msz*Dsz/2; i += 256) { h[i] = 0u; l[i] = 0u; }
    }
}

// ---------------------------------------------------------------------------
template<int MT, int NT, bool GELU, bool WSPLIT, bool WF32>
static void run_gemm(const __nv_bfloat16* Ah, const __nv_bfloat16* Al,
                     const __nv_bfloat16* Wh, const __nv_bfloat16* Wl,
                     const float* bias, float* C,
                     __nv_bfloat16* Chi, __nv_bfloat16* Clo,
                     int M, int N, int K)
{
    constexpr int BM = MT * 64;
    constexpr int BN = NT * 16;
    constexpr int ROWS = BM + BN;
    const size_t smem = (size_t)ROWS * 64 * 2 * 3;
    cudaFuncSetAttribute(mma_gemm<MT, NT, GELU, WSPLIT, WF32>,
                         cudaFuncAttributeMaxDynamicSharedMemorySize, (int)smem);
    dim3 grid(N / BN, (M + BM - 1) / BM);
    mma_gemm<MT, NT, GELU, WSPLIT, WF32><<<grid, 256, smem>>>(
        Ah, Al, Wh, Wl, bias, C, Chi, Clo, M, N, K);
}

extern "C" void kernel_launch(void* const* d_in, const int* in_sizes, int n_in,
                              void* d_out, int out_size)
{
    (void)in_sizes; (void)n_in; (void)out_size;
    const int*   eids   = (const int*)d_in[0];
    const int*   nids   = (const int*)d_in[1];
    const float* mask   = (const float*)d_in[2];
    const float* rel_emb= (const float*)d_in[3];
    const float* rp_b   = (const float*)d_in[5];
    const float* vwf    = (const float*)d_in[6];
    const float* vbp    = (const float*)d_in[7];
    const float* owf    = (const float*)d_in[8];
    const float* obp    = (const float*)d_in[9];
    const float* n1g    = (const float*)d_in[10];
    const float* n1b    = (const float*)d_in[11];
    const float* n2g    = (const float*)d_in[12];
    const float* n2b    = (const float*)d_in[13];
    const float* b1     = (const float*)d_in[15];
    const float* b2     = (const float*)d_in[17];
    const float* tqb    = (const float*)d_in[20];
    const float* tkb    = (const float*)d_in[22];
    const float* tvb    = (const float*)d_in[24];
    const float* tob    = (const float*)d_in[26];
    const float* pb     = (const float*)d_in[28];
    float* out = (float*)d_out;

    float *ptable, *states, *tmp, *tmp2, *q, *kv, *bc, *kvb, *zero;
    cudaGetSymbolAddress((void**)&ptable, g_ptable);
    cudaGetSymbolAddress((void**)&states, g_states);
    cudaGetSymbolAddress((void**)&tmp,    g_tmp);
    cudaGetSymbolAddress((void**)&tmp2,   g_tmp2);
    cudaGetSymbolAddress((void**)&q,      g_q);
    cudaGetSymbolAddress((void**)&kv,     g_kv);
    cudaGetSymbolAddress((void**)&bc,     g_bc);
    cudaGetSymbolAddress((void**)&kvb,    g_kvb);
    cudaGetSymbolAddress((void**)&zero,   g_zero);

    __nv_bfloat16 *relh, *rell, *rpwh, *rpwl, *vwTh, *vwTl, *owh, *owl;
    __nv_bfloat16 *wch, *wcl, *w1h, *w1l, *w2h, *w2l, *tqwh, *tqwl;
    __nv_bfloat16 *kvwh, *kvwl, *towh, *towl, *pwh, *pwl, *memqh, *memql;
    __nv_bfloat16 *aggh, *aggl, *sth, *stl, *hidh, *hidl;
    __nv_bfloat16 *memh, *meml, *m2h, *m2l;
    cudaGetSymbolAddress((void**)&relh, g_relh);   cudaGetSymbolAddress((void**)&rell, g_rell);
    cudaGetSymbolAddress((void**)&rpwh, g_rpwh);   cudaGetSymbolAddress((void**)&rpwl, g_rpwl);
    cudaGetSymbolAddress((void**)&vwTh, g_vwTh);   cudaGetSymbolAddress((void**)&vwTl, g_vwTl);
    cudaGetSymbolAddress((void**)&owh,  g_owh);    cudaGetSymbolAddress((void**)&owl,  g_owl);
    cudaGetSymbolAddress((void**)&wch,  g_wch);    cudaGetSymbolAddress((void**)&wcl,  g_wcl);
    cudaGetSymbolAddress((void**)&w1h,  g_w1h);    cudaGetSymbolAddress((void**)&w1l,  g_w1l);
    cudaGetSymbolAddress((void**)&w2h,  g_w2h);    cudaGetSymbolAddress((void**)&w2l,  g_w2l);
    cudaGetSymbolAddress((void**)&tqwh, g_tqwh);   cudaGetSymbolAddress((void**)&tqwl, g_tqwl);
    cudaGetSymbolAddress((void**)&kvwh, g_kvwh);   cudaGetSymbolAddress((void**)&kvwl, g_kvwl);
    cudaGetSymbolAddress((void**)&towh, g_towh);   cudaGetSymbolAddress((void**)&towl, g_towl);
    cudaGetSymbolAddress((void**)&pwh,  g_pwh);    cudaGetSymbolAddress((void**)&pwl,  g_pwl);
    cudaGetSymbolAddress((void**)&memqh,g_memqh);  cudaGetSymbolAddress((void**)&memql,g_memql);
    cudaGetSymbolAddress((void**)&aggh, g_aggh);   cudaGetSymbolAddress((void**)&aggl, g_aggl);
    cudaGetSymbolAddress((void**)&sth,  g_sth);    cudaGetSymbolAddress((void**)&stl,  g_stl);
    cudaGetSymbolAddress((void**)&hidh, g_hidh);   cudaGetSymbolAddress((void**)&hidl, g_hidl);
    cudaGetSymbolAddress((void**)&memh, g_memh);   cudaGetSymbolAddress((void**)&meml, g_meml);
    cudaGetSymbolAddress((void**)&m2h,  g_m2h);    cudaGetSymbolAddress((void**)&m2l,  g_m2l);

    // 0) split all static GEMM operands (kv weights into one concat buffer)
    {
        SJobs jb;
        const float* srcs[11] = { rel_emb, (const float*)d_in[4], owf,
                                  (const float*)d_in[14], (const float*)d_in[16],
                                  (const float*)d_in[19], (const float*)d_in[21],
                                  (const float*)d_in[23], (const float*)d_in[25],
                                  (const float*)d_in[27], (const float*)d_in[18] };
        __nv_bfloat16* his[11] = { relh, rpwh, owh, w1h, w2h, tqwh, kvwh, kvwh + DD, towh, pwh, memqh };
        __nv_bfloat16* los[11] = { rell, rpwl, owl, w1l, w2l, tqwl, kvwl, kvwl + DD, towl, pwl, memql };
        const unsigned n4[11] = { Rsz*RDsz/4, Dsz*RDsz/4, Lsz*DD/4, Lsz*4*DD/4, Lsz*4*DD/4,
                                  DD/4, DD/4, DD/4, DD/4, HLLMsz*Dsz/4, Msz*Dsz/4 };
        unsigned cum = 0;
        for (int i = 0; i < 11; i++) {
            jb.src[i] = (const float4*)srcs[i];
            jb.hi[i]  = (uint2*)his[i];
            jb.lo[i]  = (uint2*)los[i];
            cum += n4[i];
            jb.end4[i] = cum;
        }
        jb.cnt = 11;
        jb.total4 = cum;
        split_multi<<<(cum + 255) / 256, 256>>>(jb);
    }
    // vw transpose-split, combined bias precompute, kv bias concat
    transpose_split_vw<<<dim3(16, 16, Lsz), dim3(32, 8)>>>(vwf);
    bc_concat<<<Lsz * 64 + 1, 256>>>(owf, vbp, obp, tkb, tvb);
    // Wc[l] = ow[l] @ vw[l]  (fused attention-context weight), split output
    for (int l = 0; l < Lsz; l++)
        run_gemm<2,4,false,true,false>(owh + (size_t)l*DD, owl + (size_t)l*DD,
                                       vwTh + (size_t)l*DD, vwTl + (size_t)l*DD,
                                       zero, 0, wch + (size_t)l*DD, wcl + (size_t)l*DD,
                                       Dsz, Dsz, Dsz);

    // 1) project ALL relation embeddings once
    run_gemm<2,4,false,false,true>(relh, rell, rpwh, rpwl, rp_b, ptable, 0, 0, Rsz, Dsz, RDsz);
    row_norm_kernel<<<Rsz, 128>>>();

    // 2) per-edge cosine sims, top-8, aggregate
    sim_topk_agg<<<BE, 256>>>(eids, nids);

    // 3) relation-context layers (attn collapsed to one GEMM via Wc)
    for (int l = 0; l < Lsz; l++) {
        run_gemm<2,4,false,false,true>(aggh, aggl, wch + (size_t)l*DD, wcl + (size_t)l*DD,
                                       bc + l*Dsz, tmp2, 0, 0, BE, Dsz, Dsz);
        add_ln<<<BE, 256>>>(states, (l == 0) ? eids : nullptr, tmp2, states,
                            n1g + l*Dsz, n1b + l*Dsz, nullptr);
        run_gemm<2,4,true,true,false>(sth, stl, w1h + (size_t)l*4*DD, w1l + (size_t)l*4*DD,
                                      b1 + l*4*Dsz, 0, hidh, hidl, BE, 4*Dsz, Dsz);
        run_gemm<2,4,false,false,true>(hidh, hidl, w2h + (size_t)l*4*DD, w2l + (size_t)l*4*DD,
                                       b2 + l*Dsz, tmp, 0, 0, BE, Dsz, 4*Dsz);
        add_ln<<<BE, 256>>>(states, nullptr, tmp, states,
                            n2g + l*Dsz, n2b + l*Dsz, mask);
    }

    // 4) memory tokenizer (k & v fused into one GEMM)
    run_gemm<1,4,false,false,true>(memqh, memql, tqwh, tqwl, tqb, q, 0, 0, Msz, Dsz, Dsz);
    run_gemm<2,4,false,false,true>(sth, stl, kvwh, kvwl, kvb, kv, 0, 0, BE, 2*Dsz, Dsz);
    mem_attn<<<Bsz*Msz, 256>>>(mask);
    run_gemm<1,4,false,true,false>(memh, meml, towh, towl, tob, 0, m2h, m2l, Bsz*Msz, Dsz, Dsz);
    zero_noedge<<<Bsz, 256>>>(mask);

    // 5) final projection to LLM hidden size
    run_gemm<2,4,false,false,true>(m2h, m2l, pwh, pwl, pb, out, 0, 0, Bsz*Msz, HLLMsz, Dsz);
}

// round 17
// speedup vs baseline: 1.0228x; 1.0228x over previous
#include <cuda_runtime.h>
#include <cuda_bf16.h>
#include <math.h>
#include <stdint.h>

// Problem constants
#define Bsz   8
#define Esz   256
#define Nsz   32
#define Dsz   512
#define RDsz  768
#define Rsz   2000
#define Lsz   2
#define Ksel  8
#define Msz   32
#define Hsz   8
#define DHsz  64
#define HLLMsz 4096
#define BE    (Bsz*Esz)   // 2048
#define DD    (Dsz*Dsz)

// fp32 scratch
__device__ float g_ptable[Rsz*Dsz];
__device__ float g_norms[Rsz];
__device__ float g_states[BE*Dsz];
__device__ float g_tmp[BE*Dsz];
__device__ float g_tmp2[BE*Dsz];
__device__ float g_q[Msz*Dsz];
__device__ float g_kv[BE*2*Dsz];
__device__ float g_bc[Lsz*Dsz];
__device__ float g_kvb[2*Dsz];
__device__ float g_zero[Dsz];          // stays zero (static zero-init)

// bf16 hi/lo split scratch
__device__ __nv_bfloat16 g_relh[Rsz*RDsz],      g_rell[Rsz*RDsz];
__device__ __nv_bfloat16 g_rpwh[Dsz*RDsz],      g_rpwl[Dsz*RDsz];
__device__ __nv_bfloat16 g_vwTh[Lsz*DD],        g_vwTl[Lsz*DD];
__device__ __nv_bfloat16 g_owh[Lsz*DD],         g_owl[Lsz*DD];
__device__ __nv_bfloat16 g_wch[Lsz*DD],         g_wcl[Lsz*DD];
__device__ __nv_bfloat16 g_w1h[Lsz*4*DD],       g_w1l[Lsz*4*DD];
__device__ __nv_bfloat16 g_w2h[Lsz*4*DD],       g_w2l[Lsz*4*DD];
__device__ __nv_bfloat16 g_tqwh[DD],            g_tqwl[DD];
__device__ __nv_bfloat16 g_kvwh[2*DD],          g_kvwl[2*DD];
__device__ __nv_bfloat16 g_towh[DD],            g_towl[DD];
__device__ __nv_bfloat16 g_pwh[HLLMsz*Dsz],     g_pwl[HLLMsz*Dsz];
__device__ __nv_bfloat16 g_memqh[Msz*Dsz],      g_memql[Msz*Dsz];
__device__ __nv_bfloat16 g_aggh[BE*Dsz],        g_aggl[BE*Dsz];
__device__ __nv_bfloat16 g_sth[BE*Dsz],         g_stl[BE*Dsz];
__device__ __nv_bfloat16 g_hidh[BE*4*Dsz],      g_hidl[BE*4*Dsz];
__device__ __nv_bfloat16 g_memh[Bsz*Msz*Dsz],   g_meml[Bsz*Msz*Dsz];
__device__ __nv_bfloat16 g_m2h[Bsz*Msz*Dsz],    g_m2l[Bsz*Msz*Dsz];

// ---------------------------------------------------------------------------
__device__ __forceinline__ uint32_t smem_u32(const void* p) {
    uint32_t a;
    asm("{ .reg .u64 t; cvta.to.shared.u64 t, %1; cvt.u32.u64 %0, t; }"
        : "=r"(a) : "l"(p));
    return a;
}

__device__ __forceinline__ void mma_bf16(float* c, const uint32_t* a, const uint32_t* b)
{
    asm volatile(
        "mma.sync.aligned.m16n8k16.row.col.f32.bf16.bf16.f32 "
        "{%0,%1,%2,%3}, {%4,%5,%6,%7}, {%8,%9}, {%0,%1,%2,%3};"
        : "+f"(c[0]), "+f"(c[1]), "+f"(c[2]), "+f"(c[3])
        : "r"(a[0]), "r"(a[1]), "r"(a[2]), "r"(a[3]), "r"(b[0]), "r"(b[1]));
}

__device__ __forceinline__ void ldm4(uint32_t* d, uint32_t addr)
{
    asm volatile("ldmatrix.sync.aligned.m8n8.x4.shared.b16 {%0,%1,%2,%3}, [%4];"
        : "=r"(d[0]), "=r"(d[1]), "=r"(d[2]), "=r"(d[3]) : "r"(addr));
}

__device__ __forceinline__ void split2(float x, float y, uint32_t& hi, uint32_t& lo)
{
    __nv_bfloat162 h = __floats2bfloat162_rn(x, y);
    float2 hf = __bfloat1622float2(h);
    __nv_bfloat162 l = __floats2bfloat162_rn(x - hf.x, y - hf.y);
    hi = *reinterpret_cast<uint32_t*>(&h);
    lo = *reinterpret_cast<uint32_t*>(&l);
}

__device__ __forceinline__ void split_scalar(float v, __nv_bfloat16* hp, __nv_bfloat16* lp)
{
    __nv_bfloat16 h = __float2bfloat16(v);
    *hp = h;
    *lp = __float2bfloat16(v - __bfloat162float(h));
}

#define CP_ASYNC16(dst, src) \
    asm volatile("cp.async.cg.shared.global [%0], [%1], 16;" :: "r"(dst), "l"(src))
#define CP_COMMIT() asm volatile("cp.async.commit_group;" ::: "memory")

// ---------------------------------------------------------------------------
// Batched fp32 -> (hi,lo) bf16 split.
// ---------------------------------------------------------------------------
struct SJobs {
    const float4* src[12];
    uint2* hi[12];
    uint2* lo[12];
    unsigned end4[12];
    int cnt;
    unsigned total4;
};

__global__ __launch_bounds__(256)
void split_multi(SJobs jb)
{
    unsigned idx = blockIdx.x * 256u + threadIdx.x;
    if (idx >= jb.total4) return;
    int t = 0;
#pragma unroll 1
    for (int i = 0; i < jb.cnt; i++)
        if (idx < jb.end4[i]) { t = i; break; }
    unsigned start = (t == 0) ? 0u : jb.end4[t - 1];
    unsigned li = idx - start;
    float4 v = jb.src[t][li];
    uint32_t h0, l0, h1, l1;
    split2(v.x, v.y, h0, l0);
    split2(v.z, v.w, h1, l1);
    jb.hi[t][li] = make_uint2(h0, h1);
    jb.lo[t][li] = make_uint2(l0, l1);
}

// transpose-split: vw[l][t][j] -> vwT[l][j][t] as bf16 hi/lo
__global__ __launch_bounds__(256)
void transpose_split_vw(const float* __restrict__ vw)
{
    __shared__ float tile[32][33];
    int l = blockIdx.z;
    int tx = threadIdx.x, ty = threadIdx.y;
#pragma unroll
    for (int i = 0; i < 32; i += 8) {
        int trow = blockIdx.y * 32 + ty + i;
        int jcol = blockIdx.x * 32 + tx;
        tile[ty + i][tx] = vw[(size_t)l * DD + (size_t)trow * Dsz + jcol];
    }
    __syncthreads();
#pragma unroll
    for (int i = 0; i < 32; i += 8) {
        int jrow = blockIdx.x * 32 + ty + i;
        int tcol = blockIdx.y * 32 + tx;
        float v = tile[tx][ty + i];
        size_t o = (size_t)l * DD + (size_t)jrow * Dsz + tcol;
        split_scalar(v, &g_vwTh[o], &g_vwTl[o]);
    }
}

// bc[l] = ow[l] @ vb[l] + ob[l]; last block concatenates kv bias
__global__ __launch_bounds__(256)
void bc_concat(const float* __restrict__ ow, const float* __restrict__ vb,
               const float* __restrict__ ob,
               const float* __restrict__ tkb, const float* __restrict__ tvb)
{
    if (blockIdx.x == Lsz * 64) {
        for (int i = threadIdx.x; i < Dsz; i += 256) {
            g_kvb[i] = tkb[i];
            g_kvb[Dsz + i] = tvb[i];
        }
        return;
    }
    int l = blockIdx.x / 64;
    int d = (blockIdx.x % 64) * 8 + (threadIdx.x >> 5);
    int lane = threadIdx.x & 31;
    const float* owr = ow + (size_t)l * DD + (size_t)d * Dsz;
    const float* vbr = vb + l * Dsz;
    float s = 0.f;
#pragma unroll 4
    for (int t = lane; t < Dsz; t += 32)
        s = fmaf(owr[t], vbr[t], s);
    for (int o = 16; o; o >>= 1) s += __shfl_xor_sync(0xffffffffu, s, o);
    if (lane == 0)
        g_bc[l * Dsz + d] = s + ob[l * Dsz + d];
}

// ---------------------------------------------------------------------------
// bf16x3 emulated-fp32 GEMM on mma.sync.m16n8k16 + ldmatrix.x4 + cp.async.
// Pre-split bf16 (hi,lo) operands. C = A @ W^T + bias (opt exact GELU).
// 256 threads = 8 warps as 4(m) x 2(n). BM=MT*64, BN=NT*16, BK=32, 3 stages.
// ---------------------------------------------------------------------------
template<int MT, int NT, bool GELU, bool WSPLIT, bool WF32>
__global__ __launch_bounds__(256)
void mma_gemm(const __nv_bfloat16* __restrict__ Ah, const __nv_bfloat16* __restrict__ Al,
              const __nv_bfloat16* __restrict__ Wh, const __nv_bfloat16* __restrict__ Wl,
              const float* __restrict__ bias, float* __restrict__ C,
              __nv_bfloat16* __restrict__ Chi, __nv_bfloat16* __restrict__ Clo,
              int Mm, int Nn, int Kk)
{
    constexpr int BM    = MT * 64;
    constexpr int BN    = NT * 16;
    constexpr int ROWS  = BM + BN;
    constexpr int CHc   = ROWS * 8 / 256;
    constexpr int BUF   = ROWS * 64;
    constexpr int PAIRS = NT / 2;

    extern __shared__ char smraw[];
    const uint32_t sbase = smem_u32(smraw);

    const int tid  = threadIdx.x;
    const int lane = tid & 31;
    const int wid  = tid >> 5;
    const int m0 = blockIdx.y * BM;
    const int n0 = blockIdx.x * BN;
    const int mw = (wid >> 1) * (MT * 16);
    const int nw = (wid & 1) * (NT * 8);
    const int r  = lane >> 2;
    const int cq = lane & 3;

    float acc[MT][NT][4];
#pragma unroll
    for (int mt = 0; mt < MT; mt++)
#pragma unroll
        for (int j = 0; j < NT; j++)
#pragma unroll
            for (int t = 0; t < 4; t++) acc[mt][j][t] = 0.f;

    const __nv_bfloat16* gp[CHc];
    bool val[CHc];
    uint32_t soff[CHc];
#pragma unroll
    for (int i = 0; i < CHc; i++) {
        int idx = i * 256 + tid;
        int b   = idx >= ROWS * 4;
        int rem = idx - b * ROWS * 4;
        int rr  = rem >> 2;
        int q   = rem & 3;
        soff[i] = (uint32_t)(b * BUF + rr * 64 + ((q ^ ((rr >> 1) & 3)) * 16));
        const __nv_bfloat16* src;
        int grow;
        if (rr < BM) { src = b ? Al : Ah; grow = m0 + rr; val[i] = grow < Mm; }
        else         { src = b ? Wl : Wh; grow = n0 + rr - BM; val[i] = true; }
        gp[i] = src + (size_t)grow * Kk + q * 8;
    }

    const int rrA0 = mw + ((lane >> 3) & 1) * 8 + (lane & 7);
    uint32_t arow[MT];
    int aswz[MT];
#pragma unroll
    for (int mt = 0; mt < MT; mt++) {
        int rr = rrA0 + mt * 16;
        arow[mt] = (uint32_t)(rr * 64);
        aswz[mt] = (rr >> 1) & 3;
    }
    const int akk = lane >> 4;
    uint32_t brow[PAIRS];
    int bswz[PAIRS];
    const int bkk = (lane >> 3) & 1;
#pragma unroll
    for (int p = 0; p < PAIRS; p++) {
        int rrB = BM + nw + (p * 2 + (lane >> 4)) * 8 + (lane & 7);
        brow[p] = (uint32_t)(rrB * 64);
        bswz[p] = (rrB >> 1) & 3;
    }

    const int nkt = Kk >> 5;

#pragma unroll
    for (int i = 0; i < CHc; i++)
        if (val[i]) CP_ASYNC16(sbase + soff[i], gp[i]);
    CP_COMMIT();
    {
        const uint32_t dst = sbase + (uint32_t)2 * BUF;
#pragma unroll
        for (int i = 0; i < CHc; i++)
            if (val[i]) CP_ASYNC16(dst + soff[i], gp[i] + 32);
    }
    CP_COMMIT();

#pragma unroll 1
    for (int kt = 0; kt < nkt; kt++) {
        asm volatile("cp.async.wait_group 1;" ::: "memory");
        __syncthreads();
        if (kt + 2 < nkt) {
            const int sn = (kt + 2) % 3;
            const uint32_t dst = sbase + (uint32_t)(sn * 2) * BUF;
            const size_t koff = (size_t)(kt + 2) * 32;
#pragma unroll
            for (int i = 0; i < CHc; i++)
                if (val[i]) CP_ASYNC16(dst + soff[i], gp[i] + koff);
        }
        CP_COMMIT();

        const int s = kt % 3;
        const uint32_t Hb = sbase + (uint32_t)(s * 2) * BUF;
        const uint32_t Lb = Hb + BUF;
#pragma unroll
        for (int ks = 0; ks < 2; ks++) {
            uint32_t ah[MT][4], al[MT][4];
#pragma unroll
            for (int mt = 0; mt < MT; mt++) {
                const uint32_t ak = (uint32_t)(((ks * 2 + akk) ^ aswz[mt]) * 16);
                ldm4(ah[mt], Hb + arow[mt] + ak);
                ldm4(al[mt], Lb + arow[mt] + ak);
            }
#pragma unroll
            for (int p = 0; p < PAIRS; p++) {
                uint32_t bh[4], bl[4];
                const uint32_t bk = (uint32_t)(((ks * 2 + bkk) ^ bswz[p]) * 16);
                ldm4(bh, Hb + brow[p] + bk);
                ldm4(bl, Lb + brow[p] + bk);
#pragma unroll
                for (int t = 0; t < 2; t++) {
                    const int j = p * 2 + t;
#pragma unroll
                    for (int mt = 0; mt < MT; mt++) {
                        mma_bf16(acc[mt][j], ah[mt], bh + 2 * t);
                        mma_bf16(acc[mt][j], al[mt], bh + 2 * t);
                        mma_bf16(acc[mt][j], ah[mt], bl + 2 * t);
                    }
                }
            }
        }
    }

#pragma unroll
    for (int mt = 0; mt < MT; mt++) {
        const int row0 = m0 + mw + mt * 16 + r;
#pragma unroll
        for (int j = 0; j < NT; j++) {
            const int col = n0 + nw + j * 8 + cq * 2;
            const float b0v = __ldg(&bias[col]);
            const float b1v = __ldg(&bias[col + 1]);
            float v0 = acc[mt][j][0] + b0v;
            float v1 = acc[mt][j][1] + b1v;
            float v2 = acc[mt][j][2] + b0v;
            float v3 = acc[mt][j][3] + b1v;
            if (GELU) {
                v0 = 0.5f * v0 * (1.f + erff(v0 * 0.70710678118654752f));
                v1 = 0.5f * v1 * (1.f + erff(v1 * 0.70710678118654752f));
                v2 = 0.5f * v2 * (1.f + erff(v2 * 0.70710678118654752f));
                v3 = 0.5f * v3 * (1.f + erff(v3 * 0.70710678118654752f));
            }
            if (row0 < Mm) {
                const size_t o = (size_t)row0 * Nn + col;
                if (WF32) { C[o] = v0; C[o + 1] = v1; }
                if (WSPLIT) {
                    uint32_t h, l; split2(v0, v1, h, l);
                    *(uint32_t*)&Chi[o] = h; *(uint32_t*)&Clo[o] = l;
                }
            }
            if (row0 + 8 < Mm) {
                const size_t o = (size_t)(row0 + 8) * Nn + col;
                if (WF32) { C[o] = v2; C[o + 1] = v3; }
                if (WSPLIT) {
                    uint32_t h, l; split2(v2, v3, h, l);
                    *(uint32_t*)&Chi[o] = h; *(uint32_t*)&Clo[o] = l;
                }
            }
        }
    }
}

// ---------------------------------------------------------------------------
__device__ __forceinline__ float block_sum_256(float v, float* red)
{
    for (int o = 16; o; o >>= 1) v += __shfl_xor_sync(0xffffffffu, v, o);
    int w = threadIdx.x >> 5;
    if ((threadIdx.x & 31) == 0) red[w] = v;
    __syncthreads();
    float r = 0.f;
    if (threadIdx.x < 8) {
        r = red[threadIdx.x];
        for (int o = 4; o; o >>= 1) r += __shfl_xor_sync(0xffu, r, o);
        if (threadIdx.x == 0) red[0] = r;
    }
    __syncthreads();
    r = red[0];
    __syncthreads();
    return r;
}

__global__ __launch_bounds__(128)
void row_norm_kernel()
{
    int r = blockIdx.x;
    int tid = threadIdx.x;
    float4 v = ((const float4*)&g_ptable[(size_t)r * Dsz])[tid];
    float s = v.x*v.x + v.y*v.y + v.z*v.z + v.w*v.w;
    for (int o = 16; o; o >>= 1) s += __shfl_xor_sync(0xffffffffu, s, o);
    __shared__ float red[4];
    if ((tid & 31) == 0) red[tid >> 5] = s;
    __syncthreads();
    if (tid == 0)
        g_norms[r] = sqrtf(red[0] + red[1] + red[2] + red[3]);
}

__global__ __launch_bounds__(256)
void sim_topk_agg(const int* __restrict__ eids, const int* __restrict__ nids)
{
    int be = blockIdx.x;
    int tid = threadIdx.x;
    __shared__ float4 ev4[Dsz / 4];
    __shared__ float sims[Nsz];
    __shared__ int   selnid[Ksel];
    int eid = eids[be];
    if (tid < 128)
        ev4[tid] = ((const float4*)&g_ptable[(size_t)eid * Dsz])[tid];
    __syncthreads();
    float enorm = fmaxf(g_norms[eid], 1e-12f);
    int warp = tid >> 5, lane = tid & 31;
    int nid[4];
    const float4* nv[4];
#pragma unroll
    for (int t = 0; t < 4; t++) {
        nid[t] = nids[be * Nsz + warp * 4 + t];
        nv[t]  = (const float4*)&g_ptable[(size_t)nid[t] * Dsz];
    }
    float accv[4] = {0.f, 0.f, 0.f, 0.f};
#pragma unroll
    for (int j = 0; j < 4; j++) {
        float4 b = ev4[lane + 32 * j];
#pragma unroll
        for (int t = 0; t < 4; t++) {
            float4 a = nv[t][lane + 32 * j];
            accv[t] = fmaf(a.x, b.x, accv[t]);
            accv[t] = fmaf(a.y, b.y, accv[t]);
            accv[t] = fmaf(a.z, b.z, accv[t]);
            accv[t] = fmaf(a.w, b.w, accv[t]);
        }
    }
#pragma unroll
    for (int t = 0; t < 4; t++) {
        float s = accv[t];
        for (int o = 16; o; o >>= 1) s += __shfl_xor_sync(0xffffffffu, s, o);
        if (lane == 0)
            sims[warp * 4 + t] = s / (enorm * fmaxf(g_norms[nid[t]], 1e-12f));
    }
    __syncthreads();
    if (tid == 0) {
        unsigned used = 0;
        for (int j = 0; j < Ksel; j++) {
            float best = -3.402823466e38f; int bi = 0;
            for (int n = 0; n < Nsz; n++)
                if (!((used >> n) & 1u) && sims[n] > best) { best = sims[n]; bi = n; }
            used |= 1u << bi;
            selnid[j] = nids[be * Nsz + bi];
        }
    }
    __syncthreads();
    float2 s2 = make_float2(0.f, 0.f);
#pragma unroll
    for (int j = 0; j < Ksel; j++) {
        float2 vq = ((const float2*)&g_ptable[(size_t)selnid[j] * Dsz])[tid];
        s2.x += vq.x; s2.y += vq.y;
    }
    s2.x *= 0.125f; s2.y *= 0.125f;
    const size_t o = (size_t)be * Dsz + tid * 2;
    uint32_t h, l;
    split2(s2.x, s2.y, h, l);
    *(uint32_t*)&g_aggh[o] = h;
    *(uint32_t*)&g_aggl[o] = l;
}

__global__ __launch_bounds__(256)
void add_ln(const float* __restrict__ x, const int* __restrict__ xidx,
            const float* __restrict__ add,
            float* __restrict__ out, const float* __restrict__ g,
            const float* __restrict__ b, const float* __restrict__ mask)
{
    int row = blockIdx.x;
    int tid = threadIdx.x;
    __shared__ float red[8];
    size_t base = (size_t)row * Dsz;
    const float* xr = xidx ? &g_ptable[(size_t)xidx[row] * Dsz] : &x[base];
    float v0 = xr[tid]       + add[base + tid];
    float v1 = xr[tid + 256] + add[base + tid + 256];
    float total = block_sum_256(v0 + v1, red);
    float mu = total * (1.f / Dsz);
    float d0 = v0 - mu, d1 = v1 - mu;
    float var = block_sum_256(d0*d0 + d1*d1, red) * (1.f / Dsz);
    float inv = rsqrtf(var + 1e-5f);
    float mk = mask ? mask[row] : 1.f;
    float o0 = (d0 * inv * g[tid]       + b[tid])       * mk;
    float o1 = (d1 * inv * g[tid + 256] + b[tid + 256]) * mk;
    out[base + tid]       = o0;
    out[base + tid + 256] = o1;
    split_scalar(o0, &g_sth[base + tid],       &g_stl[base + tid]);
    split_scalar(o1, &g_sth[base + tid + 256], &g_stl[base + tid + 256]);
}

__global__ __launch_bounds__(256)
void mem_attn(const float* __restrict__ mask)
{
    int b = blockIdx.x >> 5;
    int m = blockIdx.x & 31;
    int tid = threadIdx.x;
    __shared__ float qs[Dsz];
    __shared__ float sc[Hsz][Esz];
    qs[tid]       = g_q[m*Dsz + tid];
    qs[tid + 256] = g_q[m*Dsz + tid + 256];
    __syncthreads();
    {
        int e = tid;
        const float* kr = &g_kv[((size_t)b*Esz + e) * (2*Dsz)];
        float mk = mask[b*Esz + e];
#pragma unroll
        for (int h = 0; h < Hsz; h++) {
            float s = 0.f;
#pragma unroll
            for (int d = 0; d < DHsz; d += 4) {
                float4 kq = *(const float4*)&kr[h*DHsz + d];
                float4 qq = *(const float4*)&qs[h*DHsz + d];
                s = fmaf(kq.x, qq.x, s); s = fmaf(kq.y, qq.y, s);
                s = fmaf(kq.z, qq.z, s); s = fmaf(kq.w, qq.w, s);
            }
            s *= 0.125f;
            sc[h][e] = (mk == 0.f) ? -3.402823466e38f : s;
        }
    }
    __syncthreads();
    {
        int w = tid >> 5, lane = tid & 31;
        float vals[8];
        float mx = -3.402823466e38f;
#pragma unroll
        for (int j = 0; j < 8; j++) { vals[j] = sc[w][lane + 32*j]; mx = fmaxf(mx, vals[j]); }
        for (int o = 16; o; o >>= 1) mx = fmaxf(mx, __shfl_xor_sync(0xffffffffu, mx, o));
        float sm = 0.f;
#pragma unroll
        for (int j = 0; j < 8; j++) { vals[j] = expf(vals[j] - mx); sm += vals[j]; }
        for (int o = 16; o; o >>= 1) sm += __shfl_xor_sync(0xffffffffu, sm, o);
        float inv = 1.f / sm;
#pragma unroll
        for (int j = 0; j < 8; j++) sc[w][lane + 32*j] = vals[j] * inv;
    }
    __syncthreads();
    float a0 = 0.f, a1 = 0.f;
    int od0 = tid, od1 = tid + 256;
    int h0 = od0 >> 6, h1 = od1 >> 6;
    for (int e = 0; e < Esz; e++) {
        const float* vr = &g_kv[((size_t)b*Esz + e) * (2*Dsz) + Dsz];
        a0 = fmaf(sc[h0][e], vr[od0], a0);
        a1 = fmaf(sc[h1][e], vr[od1], a1);
    }
    size_t ob = (size_t)blockIdx.x * Dsz;
    split_scalar(a0, &g_memh[ob + od0], &g_meml[ob + od0]);
    split_scalar(a1, &g_memh[ob + od1], &g_meml[ob + od1]);
}

__global__ __launch_bounds__(256)
void zero_noedge(const float* __restrict__ mask)
{
    int b = blockIdx.x;
    __shared__ float red[8];
    float total = block_sum_256(mask[b*Esz + threadIdx.x], red);
    if (total == 0.f) {
        uint32_t* h = (uint32_t*)&g_m2h[(size_t)b*Msz*Dsz];
        uint32_t* l = (uint32_t*)&g_m2l[(size_t)b*Msz*Dsz];
        for (int i = threadIdx.x; i < Msz*Dsz/2; i += 256) { h[i] = 0u; l[i] = 0u; }
    }
}

// ---------------------------------------------------------------------------
template<int MT, int NT, bool GELU, bool WSPLIT, bool WF32>
static void run_gemm(const __nv_bfloat16* Ah, const __nv_bfloat16* Al,
                     const __nv_bfloat16* Wh, const __nv_bfloat16* Wl,
                     const float* bias, float* C,
                     __nv_bfloat16* Chi, __nv_bfloat16* Clo,
                     int M, int N, int K)
{
    constexpr int BM = MT * 64;
    constexpr int BN = NT * 16;
    constexpr int ROWS = BM + BN;
    const size_t smem = (size_t)ROWS * 64 * 2 * 3;
    cudaFuncSetAttribute(mma_gemm<MT, NT, GELU, WSPLIT, WF32>,
                         cudaFuncAttributeMaxDynamicSharedMemorySize, (int)smem);
    dim3 grid(N / BN, (M + BM - 1) / BM);
    mma_gemm<MT, NT, GELU, WSPLIT, WF32><<<grid, 256, smem>>>(
        Ah, Al, Wh, Wl, bias, C, Chi, Clo, M, N, K);
}

extern "C" void kernel_launch(void* const* d_in, const int* in_sizes, int n_in,
                              void* d_out, int out_size)
{
    (void)in_sizes; (void)n_in; (void)out_size;
    const int*   eids   = (const int*)d_in[0];
    const int*   nids   = (const int*)d_in[1];
    const float* mask   = (const float*)d_in[2];
    const float* rel_emb= (const float*)d_in[3];
    const float* rp_b   = (const float*)d_in[5];
    const float* vwf    = (const float*)d_in[6];
    const float* vbp    = (const float*)d_in[7];
    const float* owf    = (const float*)d_in[8];
    const float* obp    = (const float*)d_in[9];
    const float* n1g    = (const float*)d_in[10];
    const float* n1b    = (const float*)d_in[11];
    const float* n2g    = (const float*)d_in[12];
    const float* n2b    = (const float*)d_in[13];
    const float* b1     = (const float*)d_in[15];
    const float* b2     = (const float*)d_in[17];
    const float* tqb    = (const float*)d_in[20];
    const float* tkb    = (const float*)d_in[22];
    const float* tvb    = (const float*)d_in[24];
    const float* tob    = (const float*)d_in[26];
    const float* pb     = (const float*)d_in[28];
    float* out = (float*)d_out;

    float *ptable, *states, *tmp, *tmp2, *q, *kv, *bc, *kvb, *zero;
    cudaGetSymbolAddress((void**)&ptable, g_ptable);
    cudaGetSymbolAddress((void**)&states, g_states);
    cudaGetSymbolAddress((void**)&tmp,    g_tmp);
    cudaGetSymbolAddress((void**)&tmp2,   g_tmp2);
    cudaGetSymbolAddress((void**)&q,      g_q);
    cudaGetSymbolAddress((void**)&kv,     g_kv);
    cudaGetSymbolAddress((void**)&bc,     g_bc);
    cudaGetSymbolAddress((void**)&kvb,    g_kvb);
    cudaGetSymbolAddress((void**)&zero,   g_zero);

    __nv_bfloat16 *relh, *rell, *rpwh, *rpwl, *vwTh, *vwTl, *owh, *owl;
    __nv_bfloat16 *wch, *wcl, *w1h, *w1l, *w2h, *w2l, *tqwh, *tqwl;
    __nv_bfloat16 *kvwh, *kvwl, *towh, *towl, *pwh, *pwl, *memqh, *memql;
    __nv_bfloat16 *aggh, *aggl, *sth, *stl, *hidh, *hidl;
    __nv_bfloat16 *memh, *meml, *m2h, *m2l;
    cudaGetSymbolAddress((void**)&relh, g_relh);   cudaGetSymbolAddress((void**)&rell, g_rell);
    cudaGetSymbolAddress((void**)&rpwh, g_rpwh);   cudaGetSymbolAddress((void**)&rpwl, g_rpwl);
    cudaGetSymbolAddress((void**)&vwTh, g_vwTh);   cudaGetSymbolAddress((void**)&vwTl, g_vwTl);
    cudaGetSymbolAddress((void**)&owh,  g_owh);    cudaGetSymbolAddress((void**)&owl,  g_owl);
    cudaGetSymbolAddress((void**)&wch,  g_wch);    cudaGetSymbolAddress((void**)&wcl,  g_wcl);
    cudaGetSymbolAddress((void**)&w1h,  g_w1h);    cudaGetSymbolAddress((void**)&w1l,  g_w1l);
    cudaGetSymbolAddress((void**)&w2h,  g_w2h);    cudaGetSymbolAddress((void**)&w2l,  g_w2l);
    cudaGetSymbolAddress((void**)&tqwh, g_tqwh);   cudaGetSymbolAddress((void**)&tqwl, g_tqwl);
    cudaGetSymbolAddress((void**)&kvwh, g_kvwh);   cudaGetSymbolAddress((void**)&kvwl, g_kvwl);
    cudaGetSymbolAddress((void**)&towh, g_towh);   cudaGetSymbolAddress((void**)&towl, g_towl);
    cudaGetSymbolAddress((void**)&pwh,  g_pwh);    cudaGetSymbolAddress((void**)&pwl,  g_pwl);
    cudaGetSymbolAddress((void**)&memqh,g_memqh);  cudaGetSymbolAddress((void**)&memql,g_memql);
    cudaGetSymbolAddress((void**)&aggh, g_aggh);   cudaGetSymbolAddress((void**)&aggl, g_aggl);
    cudaGetSymbolAddress((void**)&sth,  g_sth);    cudaGetSymbolAddress((void**)&stl,  g_stl);
    cudaGetSymbolAddress((void**)&hidh, g_hidh);   cudaGetSymbolAddress((void**)&hidl, g_hidl);
    cudaGetSymbolAddress((void**)&memh, g_memh);   cudaGetSymbolAddress((void**)&meml, g_meml);
    cudaGetSymbolAddress((void**)&m2h,  g_m2h);    cudaGetSymbolAddress((void**)&m2l,  g_m2l);

    // 0) split all static GEMM operands (kv weights into one concat buffer)
    {
        SJobs jb;
        const float* srcs[11] = { rel_emb, (const float*)d_in[4], owf,
                                  (const float*)d_in[14], (const float*)d_in[16],
                                  (const float*)d_in[19], (const float*)d_in[21],
                                  (const float*)d_in[23], (const float*)d_in[25],
                                  (const float*)d_in[27], (const float*)d_in[18] };
        __nv_bfloat16* his[11] = { relh, rpwh, owh, w1h, w2h, tqwh, kvwh, kvwh + DD, towh, pwh, memqh };
        __nv_bfloat16* los[11] = { rell, rpwl, owl, w1l, w2l, tqwl, kvwl, kvwl + DD, towl, pwl, memql };
        const unsigned n4[11] = { Rsz*RDsz/4, Dsz*RDsz/4, Lsz*DD/4, Lsz*4*DD/4, Lsz*4*DD/4,
                                  DD/4, DD/4, DD/4, DD/4, HLLMsz*Dsz/4, Msz*Dsz/4 };
        unsigned cum = 0;
        for (int i = 0; i < 11; i++) {
            jb.src[i] = (const float4*)srcs[i];
            jb.hi[i]  = (uint2*)his[i];
            jb.lo[i]  = (uint2*)los[i];
            cum += n4[i];
            jb.end4[i] = cum;
        }
        jb.cnt = 11;
        jb.total4 = cum;
        split_multi<<<(cum + 255) / 256, 256>>>(jb);
    }
    // vw transpose-split, combined bias precompute, kv bias concat
    transpose_split_vw<<<dim3(16, 16, Lsz), dim3(32, 8)>>>(vwf);
    bc_concat<<<Lsz * 64 + 1, 256>>>(owf, vbp, obp, tkb, tvb);
    // Wc[l] = ow[l] @ vw[l]: SMALL tiles (MT=1,NT=2) -> grid (16,8)=128 blocks
    for (int l = 0; l < Lsz; l++)
        run_gemm<1,2,false,true,false>(owh + (size_t)l*DD, owl + (size_t)l*DD,
                                       vwTh + (size_t)l*DD, vwTl + (size_t)l*DD,
                                       zero, 0, wch + (size_t)l*DD, wcl + (size_t)l*DD,
                                       Dsz, Dsz, Dsz);

    // 1) project ALL relation embeddings once
    run_gemm<2,4,false,false,true>(relh, rell, rpwh, rpwl, rp_b, ptable, 0, 0, Rsz, Dsz, RDsz);
    row_norm_kernel<<<Rsz, 128>>>();

    // 2) per-edge cosine sims, top-8, aggregate
    sim_topk_agg<<<BE, 256>>>(eids, nids);

    // 3) relation-context layers (attn collapsed to one GEMM via Wc)
    for (int l = 0; l < Lsz; l++) {
        run_gemm<2,4,false,false,true>(aggh, aggl, wch + (size_t)l*DD, wcl + (size_t)l*DD,
                                       bc + l*Dsz, tmp2, 0, 0, BE, Dsz, Dsz);
        add_ln<<<BE, 256>>>(states, (l == 0) ? eids : nullptr, tmp2, states,
                            n1g + l*Dsz, n1b + l*Dsz, nullptr);
        run_gemm<2,8,true,true,false>(sth, stl, w1h + (size_t)l*4*DD, w1l + (size_t)l*4*DD,
                                      b1 + l*4*Dsz, 0, hidh, hidl, BE, 4*Dsz, Dsz);
        run_gemm<2,4,false,false,true>(hidh, hidl, w2h + (size_t)l*4*DD, w2l + (size_t)l*4*DD,
                                       b2 + l*Dsz, tmp, 0, 0, BE, Dsz, 4*Dsz);
        add_ln<<<BE, 256>>>(states, nullptr, tmp, states,
                            n2g + l*Dsz, n2b + l*Dsz, mask);
    }

    // 4) memory tokenizer (k & v fused into one GEMM, wide-N tiles)
    run_gemm<1,4,false,false,true>(memqh, memql, tqwh, tqwl, tqb, q, 0, 0, Msz, Dsz, Dsz);
    run_gemm<2,8,false,false,true>(sth, stl, kvwh, kvwl, kvb, kv, 0, 0, BE, 2*Dsz, Dsz);
    mem_attn<<<Bsz*Msz, 256>>>(mask);
    run_gemm<1,4,false,true,false>(memh, meml, towh, towl, tob, 0, m2h, m2l, Bsz*Msz, Dsz, Dsz);
    zero_noedge<<<Bsz, 256>>>(mask);

    // 5) final projection to LLM hidden size (wide-N tiles, grid 128)
    run_gemm<1,8,false,false,true>(m2h, m2l, pwh, pwl, pb, out, 0, 0, Bsz*Msz, HLLMsz, Dsz);
}